// round 5
// baseline (speedup 1.0000x reference)
#include <cuda_runtime.h>
#include <math.h>
#include <stdint.h>

#define L    8192
#define DIN  128
#define HH   64
#define WW   128
#define NCH  64
#define LC   128

// ---------------- scratch (device globals; no allocation) ----------------
__device__ __align__(128) float g_w2T[320 * 256];     // (w_in@w_proj)^T [c][o]
__device__ __align__(128) float g_b2 [256];           // w_in @ b_proj
__device__ __align__(128) float g_woT[128 * 128];     // w_out^T [c][o]
__device__ __align__(128) float g_xp [DIN * L];       // xp pre-conv      [d][l]
__device__ __align__(128) float g_zt [L * DIN];       // z                [l][d]
__device__ __align__(128) float g_xsr[L * DIN];       // scan input row   [l][d]
__device__ __align__(128) float g_xsc[L * DIN];       // scan input col   [lc][d]
__device__ __align__(128) float g_dbc[4 * 40 * L];    // x_proj out       [k][r][l]
__device__ __align__(128) float g_dtv[4 * L * DIN];   // softplus dt      [k][l][d]
__device__ __align__(128) float g_bc [4 * L * 32];    // B,C per pos      [k][l][32]
__device__ __align__(128) float g_S  [4 * DIN * NCH];
__device__ __align__(128) float g_F  [4 * DIN * NCH * 16];
__device__ __align__(128) float g_hi [4 * DIN * NCH * 16];
__device__ __align__(128) float g_ys [4 * L * DIN];   // scan outputs     [k][l][d]
__device__ __align__(128) float g_ygT[DIN * L];       // merged+gated, T  [d][l]
__device__ int g_intA;

// ---------------- prep: w_out^T ----------------
__global__ void k_prep(const float* __restrict__ wout) {
    int i = blockIdx.x * 256 + threadIdx.x;
    int c = i >> 7, o = i & 127;
    g_woT[i] = wout[o * 128 + c];
}

// ---------------- prep: W2^T = (w_in @ w_proj)^T  [c=320][o=256] ---------
__global__ __launch_bounds__(256) void k_prepW(const float* __restrict__ win,
                                               const float* __restrict__ wp) {
    __shared__ float Wp[16][64];   // [m][c]
    __shared__ float Wi[16][65];   // [m][o]
    int c0 = blockIdx.x * 64, o0 = blockIdx.y * 64;
    int tid = threadIdx.x, tx = tid & 15, ty = tid >> 4;
    float acc[4][4] = {};
    for (int m0 = 0; m0 < 128; m0 += 16) {
        {
            int r = tid >> 4, cc = (tid & 15) * 4;
            *(float4*)&Wp[r][cc] = *(const float4*)(wp + (m0 + r) * 320 + c0 + cc);
        }
        for (int i = tid; i < 1024; i += 256) {
            int mm = i & 15, oo = i >> 4;
            Wi[mm][oo] = win[(o0 + oo) * 128 + m0 + mm];
        }
        __syncthreads();
#pragma unroll
        for (int mm = 0; mm < 16; mm++) {
            float cv[4], ov[4];
            *(float4*)cv = *(float4*)&Wp[mm][tx * 4];
            ov[0] = Wi[mm][ty * 4 + 0]; ov[1] = Wi[mm][ty * 4 + 1];
            ov[2] = Wi[mm][ty * 4 + 2]; ov[3] = Wi[mm][ty * 4 + 3];
#pragma unroll
            for (int ci = 0; ci < 4; ci++)
#pragma unroll
                for (int oi = 0; oi < 4; oi++)
                    acc[ci][oi] = fmaf(cv[ci], ov[oi], acc[ci][oi]);
        }
        __syncthreads();
    }
#pragma unroll
    for (int ci = 0; ci < 4; ci++)
#pragma unroll
        for (int oi = 0; oi < 4; oi++)
            g_w2T[(c0 + tx * 4 + ci) * 256 + o0 + ty * 4 + oi] = acc[ci][oi];
}

// ---------------- prep: b2 = w_in @ b_proj ----------------
__global__ void k_prepB(const float* __restrict__ win,
                        const float* __restrict__ bproj) {
    int o = threadIdx.x;
    float s = 0.f;
    for (int m = 0; m < 128; m++) s = fmaf(win[o * 128 + m], bproj[m], s);
    g_b2[o] = s;
}

// ---------------- A-structure check ----------------
__global__ void k_checkA(const float* __restrict__ A_log) {
    __shared__ int bad;
    if (threadIdx.x == 0) bad = 0;
    __syncthreads();
    for (int i = threadIdx.x; i < 4 * DIN * 16; i += blockDim.x) {
        int n = i & 15;
        float ref = logf((float)(n + 1));
        if (fabsf(A_log[i] - ref) > 1e-5f) bad = 1;
    }
    __syncthreads();
    if (threadIdx.x == 0) g_intA = bad ? 0 : 1;
}

// ---------------- GEMM: out[o][l] = sum_c WT[c][o] * U[c][l] -------------
// BL=64, BO=64, BK=16, 128 threads, double-buffered smem (LDG->regs->STS),
// per-thread 4(l) x 8(o), fragment double-buffering in the inner loop.
// SRC 0: U = concat(h,x) args, WT = g_w2T (ostride 256); EPI 1: +b2, split xp/z
// SRC 2: U = g_ygT,            WT = g_woT (ostride 128); EPI 2: h + tanh
template<int KDIM, int SRC, int EPI>
__global__ __launch_bounds__(128) void k_gemm(
    const float* __restrict__ U1, const float* __restrict__ U2,
    const float* __restrict__ hsrc, float* __restrict__ outp) {
    __shared__ float As[2][16][64];
    __shared__ float Bs[2][16][64];
    const float* WT = (SRC == 0) ? g_w2T : g_woT;
    const int ostride = (SRC == 0) ? 256 : 128;
    int tid = threadIdx.x;
    int tx = tid & 15, ty = tid >> 4;
    int l0 = blockIdx.x * 64, o0 = blockIdx.y * 64;
    int ar = tid >> 3, ac8 = (tid & 7) * 8;   // stage: row 0..15, col 0..56
    float acc[4][8] = {};
    float4 ra0, ra1, rb0, rb1;

    auto srcRow = [&](int c) -> const float* {
        if (SRC == 0) return (c < 128) ? (U1 + c * L) : (U2 + (c - 128) * L);
        else return g_ygT + c * L;
    };
    auto ldStage = [&](int k0) {
        const float* ap = srcRow(k0 + ar) + l0 + ac8;
        ra0 = *(const float4*)(ap);
        ra1 = *(const float4*)(ap + 4);
        const float* bp = WT + (k0 + ar) * ostride + o0 + ac8;
        rb0 = *(const float4*)(bp);
        rb1 = *(const float4*)(bp + 4);
    };
    auto stStage = [&](int s) {
        *(float4*)&As[s][ar][ac8]     = ra0;
        *(float4*)&As[s][ar][ac8 + 4] = ra1;
        *(float4*)&Bs[s][ar][ac8]     = rb0;
        *(float4*)&Bs[s][ar][ac8 + 4] = rb1;
    };

    const int nk = KDIM / 16;
    ldStage(0);
    stStage(0);
    __syncthreads();

#pragma unroll 1
    for (int t = 0; t < nk; t++) {
        int cur = t & 1;
        if (t + 1 < nk) ldStage((t + 1) * 16);
        float4 a  = *(const float4*)&As[cur][0][tx * 4];
        float4 b0 = *(const float4*)&Bs[cur][0][ty * 8];
        float4 b1 = *(const float4*)&Bs[cur][0][ty * 8 + 4];
#pragma unroll
        for (int kk = 0; kk < 16; kk++) {
            float4 an, b0n, b1n;
            if (kk < 15) {
                an  = *(const float4*)&As[cur][kk + 1][tx * 4];
                b0n = *(const float4*)&Bs[cur][kk + 1][ty * 8];
                b1n = *(const float4*)&Bs[cur][kk + 1][ty * 8 + 4];
            }
            float av[4] = {a.x, a.y, a.z, a.w};
            float bv[8] = {b0.x, b0.y, b0.z, b0.w, b1.x, b1.y, b1.z, b1.w};
#pragma unroll
            for (int i = 0; i < 4; i++)
#pragma unroll
                for (int j = 0; j < 8; j++)
                    acc[i][j] = fmaf(av[i], bv[j], acc[i][j]);
            if (kk < 15) { a = an; b0 = b0n; b1 = b1n; }
        }
        __syncthreads();
        if (t + 1 < nk) {
            stStage(cur ^ 1);
            __syncthreads();
        }
    }

#pragma unroll
    for (int j = 0; j < 8; j++) {
        int o = o0 + ty * 8 + j;
        int off = o * L + l0 + tx * 4;
        float4 v = make_float4(acc[0][j], acc[1][j], acc[2][j], acc[3][j]);
        if (EPI == 1) {
            float bv = g_b2[o];
            v.x += bv; v.y += bv; v.z += bv; v.w += bv;
            if (o < 128) {
                *(float4*)(g_xp + off) = v;
            } else {
                int dz = o - 128;
                int lb = l0 + tx * 4;
                g_zt[(lb + 0) * DIN + dz] = v.x;
                g_zt[(lb + 1) * DIN + dz] = v.y;
                g_zt[(lb + 2) * DIN + dz] = v.z;
                g_zt[(lb + 3) * DIN + dz] = v.w;
            }
        } else {
            float4 hv = *(const float4*)(hsrc + off);
            v.x = hv.x + tanhf(v.x);
            v.y = hv.y + tanhf(v.y);
            v.z = hv.z + tanhf(v.z);
            v.w = hv.w + tanhf(v.w);
            *(float4*)(outp + off) = v;
        }
    }
}

// ------------- fused depthwise 3x3 conv + SiLU + transpose ---------------
__global__ void k_convt(const float* __restrict__ wc,
                        const float* __restrict__ bcv) {
    __shared__ float t[32][33];
    int l0 = blockIdx.x * 32, d0 = blockIdx.y * 32;
    int tx = threadIdx.x, ty = threadIdx.y;  // 32 x 8
    int l = l0 + tx;
    int hh = l >> 7, ww = l & 127;
#pragma unroll
    for (int j = 0; j < 4; j++) {
        int d = d0 + ty + 8 * j;
        const float* src = g_xp + (d << 13);
        const float* w9 = wc + d * 9;
        float acc = bcv[d];
#pragma unroll
        for (int kh = 0; kh < 3; kh++) {
            int y = hh + kh - 1;
            if (y < 0 || y >= HH) continue;
#pragma unroll
            for (int kw = 0; kw < 3; kw++) {
                int xw = ww + kw - 1;
                if (xw < 0 || xw >= WW) continue;
                acc = fmaf(src[y * WW + xw], w9[kh * 3 + kw], acc);
            }
        }
        t[ty + 8 * j][tx] = acc / (1.f + __expf(-acc));
    }
    __syncthreads();
#pragma unroll
    for (int j = 0; j < 4; j++) {
        int l2 = l0 + ty + 8 * j;
        float v = t[tx][ty + 8 * j];
        g_xsr[l2 * DIN + d0 + tx] = v;
        int h2 = l2 >> 7, w2 = l2 & 127;
        g_xsc[(w2 * HH + h2) * DIN + d0 + tx] = v;
    }
}

// ---------------- x_proj: dbc[k] = x_proj_w[k] @ xs[k] -------------------
__global__ __launch_bounds__(256) void k_dbc(const float* __restrict__ xpw) {
    int k = blockIdx.z;
    const float* A = xpw + k * 40 * 128;
    const float* Bsrc = (k & 1) ? g_xsc : g_xsr;
    bool rev = (k >= 2);
    __shared__ float As[16][64];
    __shared__ float Bs[16][64];
    int tid = threadIdx.x;
    int tx = tid & 15, ty = tid >> 4;
    int l0 = blockIdx.x * 64;
    int arow = tid >> 2, ak = (tid & 3) * 4;
    float acc[4][4] = {};
    for (int k0 = 0; k0 < 128; k0 += 16) {
        int rr = arow < 40 ? arow : 39;
        float4 av = *(const float4*)(A + rr * 128 + k0 + ak);
        As[ak + 0][arow] = av.x; As[ak + 1][arow] = av.y;
        As[ak + 2][arow] = av.z; As[ak + 3][arow] = av.w;
        int ln = l0 + arow;
        int lsrc = rev ? (L - 1 - ln) : ln;
        float4 bv = *(const float4*)(Bsrc + lsrc * 128 + k0 + ak);
        Bs[ak + 0][arow] = bv.x; Bs[ak + 1][arow] = bv.y;
        Bs[ak + 2][arow] = bv.z; Bs[ak + 3][arow] = bv.w;
        __syncthreads();
#pragma unroll
        for (int kk = 0; kk < 16; kk++) {
            float4 a = *(float4*)&As[kk][ty * 4];
            float4 b = *(float4*)&Bs[kk][tx * 4];
            float ar[4] = {a.x, a.y, a.z, a.w};
            float br[4] = {b.x, b.y, b.z, b.w};
#pragma unroll
            for (int r = 0; r < 4; r++)
#pragma unroll
                for (int cc = 0; cc < 4; cc++)
                    acc[r][cc] = fmaf(ar[r], br[cc], acc[r][cc]);
        }
        __syncthreads();
    }
#pragma unroll
    for (int r = 0; r < 4; r++) {
        int m = ty * 4 + r;
        if (m < 40) {
#pragma unroll
            for (int cc = 0; cc < 4; cc++)
                g_dbc[(k * 40 + m) * L + l0 + tx * 4 + cc] = acc[r][cc];
        }
    }
}

// ---------------- dt = softplus(dt_w @ dts + dt_b); pack B,C -------------
__global__ __launch_bounds__(128) void k_dt(
    const float* __restrict__ dtw, const float* __restrict__ dtbias) {
    int k = blockIdx.y;
    int l0 = blockIdx.x * 32;
    int d = threadIdx.x;
    __shared__ float sd[40][33];
    for (int i = threadIdx.x; i < 40 * 32; i += 128) {
        int r = i >> 5, j = i & 31;
        sd[r][j] = g_dbc[(k * 40 + r) * L + l0 + j];
    }
    __syncthreads();
    float wreg[8];
#pragma unroll
    for (int r = 0; r < 8; r++) wreg[r] = dtw[(k * DIN + d) * 8 + r];
    float bv = dtbias[k * DIN + d];
    for (int j = 0; j < 32; j++) {
        float acc = bv;
#pragma unroll
        for (int r = 0; r < 8; r++) acc = fmaf(wreg[r], sd[r][j], acc);
        float sp = (acc > 20.f) ? acc : log1pf(__expf(acc));
        g_dtv[(k * L + l0 + j) * DIN + d] = sp;
    }
    for (int i = threadIdx.x; i < 32 * 32; i += 128) {
        int n = i >> 5, j = i & 31;
        g_bc[(k * L + l0 + j) * 32 + n] = sd[8 + n][j];
    }
}

// ---------------- a_n = exp(dt * A_n) ----------------
__device__ __forceinline__ void compute_a(float dtv, const float* An, bool ia,
                                          float* a) {
    if (ia) {
        float r1 = __expf(-dtv);
        float r2 = r1 * r1, r4 = r2 * r2, r8 = r4 * r4;
        a[0] = r1;       a[1] = r2;       a[2] = r2 * r1;  a[3] = r4;
        a[4] = r4 * r1;  a[5] = r4 * r2;  a[6] = r4 * a[2]; a[7] = r8;
        a[8] = r8 * r1;  a[9] = r8 * r2;  a[10] = r8 * a[2]; a[11] = r8 * r4;
        a[12] = r8 * a[4]; a[13] = r8 * a[5]; a[14] = r8 * a[6]; a[15] = r8 * r8;
    } else {
#pragma unroll
        for (int n = 0; n < 16; n++) a[n] = __expf(An[n] * dtv);
    }
}

// ---------------- scan phase 1 ----------------
__global__ __launch_bounds__(128) void k_scan1(const float* __restrict__ A_log) {
    int c = blockIdx.x, k = blockIdx.y, d = threadIdx.x;
    bool ia = (g_intA != 0);
    float An[16];
    if (!ia) {
#pragma unroll
        for (int n = 0; n < 16; n++) An[n] = -__expf(A_log[(k * DIN + d) * 16 + n]);
    }
    const float* usrc = (k & 1) ? g_xsc : g_xsr;
    bool rev = (k >= 2);
    float hr[16];
#pragma unroll
    for (int n = 0; n < 16; n++) hr[n] = 0.f;
    float S = 0.f;
    const float* dtp = g_dtv + k * L * DIN;
    for (int i = 0; i < LC; i++) {
        int l = c * LC + i;
        float dtv = dtp[l * DIN + d];
        int lu = rev ? (L - 1 - l) : l;
        float uv = usrc[lu * DIN + d];
        float du = dtv * uv;
        S += dtv;
        const float4* bp = (const float4*)(g_bc + (k * L + l) * 32);
        float4 b0 = bp[0], b1 = bp[1], b2 = bp[2], b3 = bp[3];
        float bb[16] = {b0.x, b0.y, b0.z, b0.w, b1.x, b1.y, b1.z, b1.w,
                        b2.x, b2.y, b2.z, b2.w, b3.x, b3.y, b3.z, b3.w};
        float a[16];
        compute_a(dtv, An, ia, a);
#pragma unroll
        for (int n = 0; n < 16; n++) hr[n] = fmaf(a[n], hr[n], du * bb[n]);
    }
    int base = (k * DIN + d) * NCH + c;
    g_S[base] = S;
#pragma unroll
    for (int n = 0; n < 16; n++) g_F[base * 16 + n] = hr[n];
}

// ---------------- scan phase 2 ----------------
__global__ __launch_bounds__(256) void k_scan2(const float* __restrict__ A_log) {
    int n = threadIdx.x & 15;
    int d = blockIdx.x * 16 + (threadIdx.x >> 4);
    int k = blockIdx.y;
    bool ia = (g_intA != 0);
    float An = ia ? -(float)(n + 1) : -__expf(A_log[(k * DIN + d) * 16 + n]);
    float h = 0.f;
    int base = (k * DIN + d) * NCH;
    for (int c = 0; c < NCH; c++) {
        g_hi[(base + c) * 16 + n] = h;
        float P = __expf(An * g_S[base + c]);
        h = fmaf(P, h, g_F[(base + c) * 16 + n]);
    }
}

// ---------------- scan phase 3 ----------------
__global__ __launch_bounds__(128) void k_scan3(
    const float* __restrict__ A_log, const float* __restrict__ Dssm) {
    int c = blockIdx.x, k = blockIdx.y, d = threadIdx.x;
    bool ia = (g_intA != 0);
    float An[16];
    if (!ia) {
#pragma unroll
        for (int n = 0; n < 16; n++) An[n] = -__expf(A_log[(k * DIN + d) * 16 + n]);
    }
    const float* usrc = (k & 1) ? g_xsc : g_xsr;
    bool rev = (k >= 2);
    float Dv = Dssm[k * DIN + d];
    int base = (k * DIN + d) * NCH + c;
    float hr[16];
#pragma unroll
    for (int n = 0; n < 16; n++) hr[n] = g_hi[base * 16 + n];
    const float* dtp = g_dtv + k * L * DIN;
    for (int i = 0; i < LC; i++) {
        int l = c * LC + i;
        float dtv = dtp[l * DIN + d];
        int lu = rev ? (L - 1 - l) : l;
        float uv = usrc[lu * DIN + d];
        float du = dtv * uv;
        const float4* bp = (const float4*)(g_bc + (k * L + l) * 32);
        float4 b0 = bp[0], b1 = bp[1], b2 = bp[2], b3 = bp[3];
        float4 c0 = bp[4], c1 = bp[5], c2 = bp[6], c3 = bp[7];
        float bb[16] = {b0.x, b0.y, b0.z, b0.w, b1.x, b1.y, b1.z, b1.w,
                        b2.x, b2.y, b2.z, b2.w, b3.x, b3.y, b3.z, b3.w};
        float cc[16] = {c0.x, c0.y, c0.z, c0.w, c1.x, c1.y, c1.z, c1.w,
                        c2.x, c2.y, c2.z, c2.w, c3.x, c3.y, c3.z, c3.w};
        float a[16];
        compute_a(dtv, An, ia, a);
        float y4[4] = {0.f, 0.f, 0.f, 0.f};
#pragma unroll
        for (int n = 0; n < 16; n++) {
            hr[n] = fmaf(a[n], hr[n], du * bb[n]);
            y4[n & 3] = fmaf(hr[n], cc[n], y4[n & 3]);
        }
        float y = fmaf(Dv, uv, (y4[0] + y4[1]) + (y4[2] + y4[3]));
        g_ys[(k * L + l) * DIN + d] = y;
    }
}

// ---------------- cross-merge + LN + SiLU(z) gate -> ygT[d][l] -----------
__global__ __launch_bounds__(256) void k_merge(
    const float* __restrict__ lng, const float* __restrict__ lnb) {
    __shared__ float ts[32][133];
    int l0 = blockIdx.x * 32;
    int lane = threadIdx.x & 31, w = threadIdx.x >> 5;
    float g4[4], b4[4];
    *(float4*)g4 = *(const float4*)(lng + lane * 4);
    *(float4*)b4 = *(const float4*)(lnb + lane * 4);
#pragma unroll
    for (int q = 0; q < 4; q++) {
        int ll = w * 4 + q;
        int l = l0 + ll;
        int hh = l >> 7, ww = l & 127;
        int lc = ww * HH + hh;
        float4 y0 = *(const float4*)(g_ys + (0 * L + l) * DIN + lane * 4);
        float4 y2 = *(const float4*)(g_ys + (2 * L + (L - 1 - l)) * DIN + lane * 4);
        float4 y1 = *(const float4*)(g_ys + (1 * L + lc) * DIN + lane * 4);
        float4 y3 = *(const float4*)(g_ys + (3 * L + (L - 1 - lc)) * DIN + lane * 4);
        float yv[4] = {y0.x + y2.x + y1.x + y3.x, y0.y + y2.y + y1.y + y3.y,
                       y0.z + y2.z + y1.z + y3.z, y0.w + y2.w + y1.w + y3.w};
        float s = yv[0] + yv[1] + yv[2] + yv[3];
        float s2 = yv[0] * yv[0] + yv[1] * yv[1] + yv[2] * yv[2] + yv[3] * yv[3];
#pragma unroll
        for (int o = 16; o > 0; o >>= 1) {
            s  += __shfl_xor_sync(0xffffffffu, s, o);
            s2 += __shfl_xor_sync(0xffffffffu, s2, o);
        }
        float mu = s * (1.f / 128.f);
        float var = s2 * (1.f / 128.f) - mu * mu;
        float rstd = rsqrtf(var + 1e-5f);
        float4 zv = *(const float4*)(g_zt + l * DIN + lane * 4);
        float zz[4] = {zv.x, zv.y, zv.z, zv.w};
#pragma unroll
        for (int m = 0; m < 4; m++) {
            float gv = (yv[m] - mu) * rstd * g4[m] + b4[m];
            float sz = zz[m] / (1.f + __expf(-zz[m]));
            ts[ll][lane * 4 + m] = gv * sz;
        }
    }
    __syncthreads();
    int d = threadIdx.x >> 1;
    int cb = (threadIdx.x & 1) * 16;
#pragma unroll
    for (int i = 0; i < 16; i += 4) {
        float4 v = make_float4(ts[cb + i + 0][d], ts[cb + i + 1][d],
                               ts[cb + i + 2][d], ts[cb + i + 3][d]);
        *(float4*)(g_ygT + d * L + l0 + cb + i) = v;
    }
}

// ---------------- launch ----------------
extern "C" void kernel_launch(void* const* d_in, const int* in_sizes, int n_in,
                              void* d_out, int out_size) {
    const float* h       = (const float*)d_in[0];
    const float* x       = (const float*)d_in[1];
    const float* w_proj  = (const float*)d_in[2];
    const float* b_proj  = (const float*)d_in[3];
    const float* w_in    = (const float*)d_in[4];
    const float* w_conv  = (const float*)d_in[5];
    const float* b_conv  = (const float*)d_in[6];
    const float* x_proj_w= (const float*)d_in[7];
    const float* dt_w    = (const float*)d_in[8];
    const float* dt_b    = (const float*)d_in[9];
    const float* A_log   = (const float*)d_in[10];
    const float* D_ssm   = (const float*)d_in[11];
    const float* ln_g    = (const float*)d_in[12];
    const float* ln_b    = (const float*)d_in[13];
    const float* w_out   = (const float*)d_in[14];
    float* out = (float*)d_out;

    k_prep  <<<64, 256>>>(w_out);
    k_prepW <<<dim3(5, 4), 256>>>(w_in, w_proj);
    k_prepB <<<1, 256>>>(w_in, b_proj);
    k_checkA<<<1, 256>>>(A_log);
    // Fused: [xp; z] = (w_in@w_proj) @ [h;x] + w_in@b_proj   (K=320, O=256)
    k_gemm<320, 0, 1><<<dim3(128, 4), 128>>>(h, x, nullptr, nullptr);
    k_convt <<<dim3(256, 4), dim3(32, 8)>>>(w_conv, b_conv);
    k_dbc   <<<dim3(128, 1, 4), 256>>>(x_proj_w);
    k_dt    <<<dim3(256, 4), 128>>>(dt_w, dt_b);
    k_scan1 <<<dim3(NCH, 4), 128>>>(A_log);
    k_scan2 <<<dim3(8, 4), 256>>>(A_log);
    k_scan3 <<<dim3(NCH, 4), 128>>>(A_log, D_ssm);
    k_merge <<<256, 256>>>(ln_g, ln_b);
    // FINAL: out = h + tanh(w_out @ ygT)           (K=128, O=128)
    k_gemm<128, 2, 2><<<dim3(128, 2), 128>>>(nullptr, nullptr, h, out);
}

// round 8
// speedup vs baseline: 1.0760x; 1.0760x over previous
#include <cuda_runtime.h>
#include <math.h>

#define L    8192
#define DIN  128
#define HH   64
#define WW   128
#define NCH  64
#define LC   128

// ---------------- scratch (device globals; no allocation) ----------------
__device__ float g_hxp[DIN * L];        // after w_proj GEMM       [o][l]
__device__ float g_xp [DIN * L];        // xp pre-conv             [d][l]
__device__ float g_zt [L * DIN];        // z                       [l][d]
__device__ float g_xsr[L * DIN];        // row-major scan input    [l][d]
__device__ float g_xsc[L * DIN];        // col-major scan input    [lc][d]
__device__ float g_dbc[4 * 40 * L];     // x_proj output           [k][r][l]
__device__ float g_dtv[4 * L * DIN];    // softplus dt             [k][l][d]
__device__ float g_bc [4 * L * 32];     // B(16),C(16) per pos     [k][l][32]
__device__ float g_S  [4 * DIN * NCH];          // sum dt per chunk
__device__ float g_F  [4 * DIN * NCH * 16];     // chunk-local final state
__device__ float g_hi [4 * DIN * NCH * 16];     // chunk initial state
__device__ float g_ys [4 * L * DIN];    // scan outputs            [k][l][d]
__device__ float g_yg [L * DIN];        // merged+LN+gated         [l][d]
__device__ int   g_intA;

// ---------------- A-structure check: A_log == log(1..16)? ----------------
__global__ __launch_bounds__(1024) void k_checkA(const float* __restrict__ A_log) {
    __shared__ float ref[16];
    __shared__ int bad;
    int tid = threadIdx.x;
    if (tid < 16) ref[tid] = logf((float)(tid + 1));
    if (tid == 0) bad = 0;
    __syncthreads();
    for (int i = tid; i < 4 * DIN * 16; i += 1024)
        if (fabsf(A_log[i] - ref[i & 15]) > 1e-5f) bad = 1;
    __syncthreads();
    if (tid == 0) g_intA = bad ? 0 : 1;
}

// ---------------- GEMM1: hxp = w_proj @ concat(h,x) + b_proj -------------
__global__ __launch_bounds__(256) void k_gemm1(
    const float* __restrict__ hsrc, const float* __restrict__ xsrc,
    const float* __restrict__ w,    const float* __restrict__ bias) {
    __shared__ float As[16][64];
    __shared__ float Bs[16][64];
    int tid = threadIdx.x;
    int tx = tid & 15, ty = tid >> 4;
    int l0 = blockIdx.x * 64, o0 = blockIdx.y * 64;
    int arow = tid >> 2, ak = (tid & 3) * 4;
    int bk = tid >> 4, bj = (tid & 15) * 4;
    float acc[4][4] = {};
    for (int k0 = 0; k0 < 320; k0 += 16) {
        float4 av = *(const float4*)(w + (o0 + arow) * 320 + k0 + ak);
        As[ak + 0][arow] = av.x; As[ak + 1][arow] = av.y;
        As[ak + 2][arow] = av.z; As[ak + 3][arow] = av.w;
        int c = k0 + bk;
        const float* bp = (c < 128) ? (hsrc + c * L) : (xsrc + (c - 128) * L);
        *(float4*)&Bs[bk][bj] = *(const float4*)(bp + l0 + bj);
        __syncthreads();
#pragma unroll
        for (int kk = 0; kk < 16; kk++) {
            float4 a = *(float4*)&As[kk][ty * 4];
            float4 b = *(float4*)&Bs[kk][tx * 4];
            float ar[4] = {a.x, a.y, a.z, a.w};
            float br[4] = {b.x, b.y, b.z, b.w};
#pragma unroll
            for (int r = 0; r < 4; r++)
#pragma unroll
                for (int cc = 0; cc < 4; cc++)
                    acc[r][cc] = fmaf(ar[r], br[cc], acc[r][cc]);
        }
        __syncthreads();
    }
#pragma unroll
    for (int r = 0; r < 4; r++) {
        int o = o0 + ty * 4 + r;
        float bv = bias[o];
#pragma unroll
        for (int cc = 0; cc < 4; cc++)
            g_hxp[o * L + l0 + tx * 4 + cc] = acc[r][cc] + bv;
    }
}

// ---------------- GEMM2: xz = w_in @ hxp; split into xp / z^T ------------
__global__ __launch_bounds__(256) void k_gemm2(const float* __restrict__ w) {
    __shared__ float As[16][64];
    __shared__ float Bs[16][64];
    int tid = threadIdx.x;
    int tx = tid & 15, ty = tid >> 4;
    int l0 = blockIdx.x * 64, o0 = blockIdx.y * 64;
    int arow = tid >> 2, ak = (tid & 3) * 4;
    int bk = tid >> 4, bj = (tid & 15) * 4;
    float acc[4][4] = {};
    for (int k0 = 0; k0 < 128; k0 += 16) {
        float4 av = *(const float4*)(w + (o0 + arow) * 128 + k0 + ak);
        As[ak + 0][arow] = av.x; As[ak + 1][arow] = av.y;
        As[ak + 2][arow] = av.z; As[ak + 3][arow] = av.w;
        *(float4*)&Bs[bk][bj] = *(const float4*)(g_hxp + (k0 + bk) * L + l0 + bj);
        __syncthreads();
#pragma unroll
        for (int kk = 0; kk < 16; kk++) {
            float4 a = *(float4*)&As[kk][ty * 4];
            float4 b = *(float4*)&Bs[kk][tx * 4];
            float ar[4] = {a.x, a.y, a.z, a.w};
            float br[4] = {b.x, b.y, b.z, b.w};
#pragma unroll
            for (int r = 0; r < 4; r++)
#pragma unroll
                for (int cc = 0; cc < 4; cc++)
                    acc[r][cc] = fmaf(ar[r], br[cc], acc[r][cc]);
        }
        __syncthreads();
    }
#pragma unroll
    for (int r = 0; r < 4; r++) {
        int o = o0 + ty * 4 + r;
#pragma unroll
        for (int cc = 0; cc < 4; cc++) {
            int l = l0 + tx * 4 + cc;
            float v = acc[r][cc];
            if (o < 128) g_xp[o * L + l] = v;
            else         g_zt[l * DIN + (o - 128)] = v;
        }
    }
}

// ------------- fused depthwise 3x3 conv + SiLU + transpose ---------------
__global__ void k_convt(const float* __restrict__ wc,
                        const float* __restrict__ bcv) {
    __shared__ float t[32][33];
    int l0 = blockIdx.x * 32, d0 = blockIdx.y * 32;
    int tx = threadIdx.x, ty = threadIdx.y;  // 32 x 8
    int l = l0 + tx;
    int hh = l >> 7, ww = l & 127;
#pragma unroll
    for (int j = 0; j < 4; j++) {
        int d = d0 + ty + 8 * j;
        const float* src = g_xp + (d << 13);
        const float* w9 = wc + d * 9;
        float acc = bcv[d];
#pragma unroll
        for (int kh = 0; kh < 3; kh++) {
            int y = hh + kh - 1;
            if (y < 0 || y >= HH) continue;
#pragma unroll
            for (int kw = 0; kw < 3; kw++) {
                int xw = ww + kw - 1;
                if (xw < 0 || xw >= WW) continue;
                acc = fmaf(src[y * WW + xw], w9[kh * 3 + kw], acc);
            }
        }
        t[ty + 8 * j][tx] = acc / (1.f + __expf(-acc));
    }
    __syncthreads();
#pragma unroll
    for (int j = 0; j < 4; j++) {
        int l2 = l0 + ty + 8 * j;
        float v = t[tx][ty + 8 * j];
        g_xsr[l2 * DIN + d0 + tx] = v;
        int h2 = l2 >> 7, w2 = l2 & 127;
        g_xsc[(w2 * HH + h2) * DIN + d0 + tx] = v;
    }
}

// ---------------- x_proj: dbc[k] = x_proj_w[k] @ xs[k]  (NT GEMM) --------
__global__ __launch_bounds__(256) void k_dbc(const float* __restrict__ xpw) {
    int k = blockIdx.z;
    const float* A = xpw + k * 40 * 128;
    const float* Bsrc = (k & 1) ? g_xsc : g_xsr;
    bool rev = (k >= 2);
    __shared__ float As[16][64];
    __shared__ float Bs[16][64];
    int tid = threadIdx.x;
    int tx = tid & 15, ty = tid >> 4;
    int l0 = blockIdx.x * 64;
    int arow = tid >> 2, ak = (tid & 3) * 4;
    float acc[4][4] = {};
    for (int k0 = 0; k0 < 128; k0 += 16) {
        int rr = arow < 40 ? arow : 39;
        float4 av = *(const float4*)(A + rr * 128 + k0 + ak);
        As[ak + 0][arow] = av.x; As[ak + 1][arow] = av.y;
        As[ak + 2][arow] = av.z; As[ak + 3][arow] = av.w;
        int ln = l0 + arow;
        int lsrc = rev ? (L - 1 - ln) : ln;
        float4 bv = *(const float4*)(Bsrc + lsrc * 128 + k0 + ak);
        Bs[ak + 0][arow] = bv.x; Bs[ak + 1][arow] = bv.y;
        Bs[ak + 2][arow] = bv.z; Bs[ak + 3][arow] = bv.w;
        __syncthreads();
#pragma unroll
        for (int kk = 0; kk < 16; kk++) {
            float4 a = *(float4*)&As[kk][ty * 4];
            float4 b = *(float4*)&Bs[kk][tx * 4];
            float ar[4] = {a.x, a.y, a.z, a.w};
            float br[4] = {b.x, b.y, b.z, b.w};
#pragma unroll
            for (int r = 0; r < 4; r++)
#pragma unroll
                for (int cc = 0; cc < 4; cc++)
                    acc[r][cc] = fmaf(ar[r], br[cc], acc[r][cc]);
        }
        __syncthreads();
    }
#pragma unroll
    for (int r = 0; r < 4; r++) {
        int m = ty * 4 + r;
        if (m < 40) {
#pragma unroll
            for (int cc = 0; cc < 4; cc++)
                g_dbc[(k * 40 + m) * L + l0 + tx * 4 + cc] = acc[r][cc];
        }
    }
}

// ---------------- dt = softplus(dt_w @ dts + dt_b); pack B,C -------------
__global__ __launch_bounds__(128) void k_dt(
    const float* __restrict__ dtw, const float* __restrict__ dtbias) {
    int k = blockIdx.y;
    int l0 = blockIdx.x * 32;
    int d = threadIdx.x;
    __shared__ float sd[40][33];
    for (int i = threadIdx.x; i < 40 * 32; i += 128) {
        int r = i >> 5, j = i & 31;
        sd[r][j] = g_dbc[(k * 40 + r) * L + l0 + j];
    }
    __syncthreads();
    float wreg[8];
#pragma unroll
    for (int r = 0; r < 8; r++) wreg[r] = dtw[(k * DIN + d) * 8 + r];
    float bv = dtbias[k * DIN + d];
    for (int j = 0; j < 32; j++) {
        float acc = bv;
#pragma unroll
        for (int r = 0; r < 8; r++) acc = fmaf(wreg[r], sd[r][j], acc);
        float sp = (acc > 20.f) ? acc : log1pf(__expf(acc));
        g_dtv[(k * L + l0 + j) * DIN + d] = sp;
    }
    for (int i = threadIdx.x; i < 32 * 32; i += 128) {
        int n = i >> 5, j = i & 31;
        g_bc[(k * L + l0 + j) * 32 + n] = sd[8 + n][j];
    }
}

// ---------------- a_n = exp(dt * A_n) helpers ----------------------------
__device__ __forceinline__ void compute_a(float dtv, const float* An, bool ia,
                                          float* a) {
    if (ia) {  // A_n = -(n+1): a_n = r^(n+1), r = exp(-dt)
        float r1 = __expf(-dtv);
        float r2 = r1 * r1, r4 = r2 * r2, r8 = r4 * r4;
        a[0] = r1;       a[1] = r2;       a[2] = r2 * r1;  a[3] = r4;
        a[4] = r4 * r1;  a[5] = r4 * r2;  a[6] = r4 * a[2]; a[7] = r8;
        a[8] = r8 * r1;  a[9] = r8 * r2;  a[10] = r8 * a[2]; a[11] = r8 * r4;
        a[12] = r8 * a[4]; a[13] = r8 * a[5]; a[14] = r8 * a[6]; a[15] = r8 * r8;
    } else {
#pragma unroll
        for (int n = 0; n < 16; n++) a[n] = __expf(An[n] * dtv);
    }
}

// ---------------- scan phase 1: chunk-local (F, sum-dt) ------------------
__global__ __launch_bounds__(128) void k_scan1(const float* __restrict__ A_log) {
    int c = blockIdx.x, k = blockIdx.y, d = threadIdx.x;
    bool ia = (g_intA != 0);
    float An[16];
    if (!ia) {
#pragma unroll
        for (int n = 0; n < 16; n++) An[n] = -__expf(A_log[(k * DIN + d) * 16 + n]);
    }
    const float* usrc = (k & 1) ? g_xsc : g_xsr;
    bool rev = (k >= 2);
    float hr[16];
#pragma unroll
    for (int n = 0; n < 16; n++) hr[n] = 0.f;
    float S = 0.f;
    const float* dtp = g_dtv + k * L * DIN;
    for (int i = 0; i < LC; i++) {
        int l = c * LC + i;
        float dtv = dtp[l * DIN + d];
        int lu = rev ? (L - 1 - l) : l;
        float uv = usrc[lu * DIN + d];
        float du = dtv * uv;
        S += dtv;
        const float4* bp = (const float4*)(g_bc + (k * L + l) * 32);
        float4 b0 = bp[0], b1 = bp[1], b2 = bp[2], b3 = bp[3];
        float bb[16] = {b0.x, b0.y, b0.z, b0.w, b1.x, b1.y, b1.z, b1.w,
                        b2.x, b2.y, b2.z, b2.w, b3.x, b3.y, b3.z, b3.w};
        float a[16];
        compute_a(dtv, An, ia, a);
#pragma unroll
        for (int n = 0; n < 16; n++) hr[n] = fmaf(a[n], hr[n], du * bb[n]);
    }
    int base = (k * DIN + d) * NCH + c;
    g_S[base] = S;
#pragma unroll
    for (int n = 0; n < 16; n++) g_F[base * 16 + n] = hr[n];
}

// ---------------- scan phase 2: cross-chunk prefix -----------------------
__global__ __launch_bounds__(256) void k_scan2(const float* __restrict__ A_log) {
    int n = threadIdx.x & 15;
    int d = blockIdx.x * 16 + (threadIdx.x >> 4);
    int k = blockIdx.y;
    bool ia = (g_intA != 0);
    float An = ia ? -(float)(n + 1) : -__expf(A_log[(k * DIN + d) * 16 + n]);
    float h = 0.f;
    int base = (k * DIN + d) * NCH;
    for (int c = 0; c < NCH; c++) {
        g_hi[(base + c) * 16 + n] = h;
        float P = __expf(An * g_S[base + c]);
        h = fmaf(P, h, g_F[(base + c) * 16 + n]);
    }
}

// ---------------- scan phase 3: replay with init, emit y -----------------
__global__ __launch_bounds__(128) void k_scan3(
    const float* __restrict__ A_log, const float* __restrict__ Dssm) {
    int c = blockIdx.x, k = blockIdx.y, d = threadIdx.x;
    bool ia = (g_intA != 0);
    float An[16];
    if (!ia) {
#pragma unroll
        for (int n = 0; n < 16; n++) An[n] = -__expf(A_log[(k * DIN + d) * 16 + n]);
    }
    const float* usrc = (k & 1) ? g_xsc : g_xsr;
    bool rev = (k >= 2);
    float Dv = Dssm[k * DIN + d];
    int base = (k * DIN + d) * NCH + c;
    float hr[16];
#pragma unroll
    for (int n = 0; n < 16; n++) hr[n] = g_hi[base * 16 + n];
    const float* dtp = g_dtv + k * L * DIN;
    for (int i = 0; i < LC; i++) {
        int l = c * LC + i;
        float dtv = dtp[l * DIN + d];
        int lu = rev ? (L - 1 - l) : l;
        float uv = usrc[lu * DIN + d];
        float du = dtv * uv;
        const float4* bp = (const float4*)(g_bc + (k * L + l) * 32);
        float4 b0 = bp[0], b1 = bp[1], b2 = bp[2], b3 = bp[3];
        float4 c0 = bp[4], c1 = bp[5], c2 = bp[6], c3 = bp[7];
        float bb[16] = {b0.x, b0.y, b0.z, b0.w, b1.x, b1.y, b1.z, b1.w,
                        b2.x, b2.y, b2.z, b2.w, b3.x, b3.y, b3.z, b3.w};
        float cc[16] = {c0.x, c0.y, c0.z, c0.w, c1.x, c1.y, c1.z, c1.w,
                        c2.x, c2.y, c2.z, c2.w, c3.x, c3.y, c3.z, c3.w};
        float a[16];
        compute_a(dtv, An, ia, a);
        float y4[4] = {0.f, 0.f, 0.f, 0.f};
#pragma unroll
        for (int n = 0; n < 16; n++) {
            hr[n] = fmaf(a[n], hr[n], du * bb[n]);
            y4[n & 3] = fmaf(hr[n], cc[n], y4[n & 3]);
        }
        float y = fmaf(Dv, uv, (y4[0] + y4[1]) + (y4[2] + y4[3]));
        g_ys[(k * L + l) * DIN + d] = y;
    }
}

// ---------------- cross-merge + LN + SiLU(z) gate -> yg[l][d] ------------
__global__ __launch_bounds__(256) void k_merge(
    const float* __restrict__ lng, const float* __restrict__ lnb) {
    int l0 = blockIdx.x * 32;
    int lane = threadIdx.x & 31, w = threadIdx.x >> 5;
    float g4[4], b4[4];
    *(float4*)g4 = *(const float4*)(lng + lane * 4);
    *(float4*)b4 = *(const float4*)(lnb + lane * 4);
#pragma unroll
    for (int q = 0; q < 4; q++) {
        int l = l0 + w * 4 + q;
        int hh = l >> 7, ww = l & 127;
        int lc = ww * HH + hh;
        float4 y0 = *(const float4*)(g_ys + (0 * L + l) * DIN + lane * 4);
        float4 y2 = *(const float4*)(g_ys + (2 * L + (L - 1 - l)) * DIN + lane * 4);
        float4 y1 = *(const float4*)(g_ys + (1 * L + lc) * DIN + lane * 4);
        float4 y3 = *(const float4*)(g_ys + (3 * L + (L - 1 - lc)) * DIN + lane * 4);
        float yv[4] = {y0.x + y2.x + y1.x + y3.x, y0.y + y2.y + y1.y + y3.y,
                       y0.z + y2.z + y1.z + y3.z, y0.w + y2.w + y1.w + y3.w};
        float s = yv[0] + yv[1] + yv[2] + yv[3];
        float s2 = yv[0] * yv[0] + yv[1] * yv[1] + yv[2] * yv[2] + yv[3] * yv[3];
#pragma unroll
        for (int o = 16; o > 0; o >>= 1) {
            s  += __shfl_xor_sync(0xffffffffu, s, o);
            s2 += __shfl_xor_sync(0xffffffffu, s2, o);
        }
        float mu = s * (1.f / 128.f);
        float var = s2 * (1.f / 128.f) - mu * mu;
        float rstd = rsqrtf(var + 1e-5f);
        float4 zv = *(const float4*)(g_zt + l * DIN + lane * 4);
        float zz[4] = {zv.x, zv.y, zv.z, zv.w};
        float4 ov;
        float* op = (float*)&ov;
#pragma unroll
        for (int m = 0; m < 4; m++) {
            float gv = (yv[m] - mu) * rstd * g4[m] + b4[m];
            float sz = zz[m] / (1.f + __expf(-zz[m]));
            op[m] = gv * sz;
        }
        *(float4*)(g_yg + l * DIN + lane * 4) = ov;
    }
}

// ---------------- final: out = h + tanh(w_out @ yg)  (NT GEMM) -----------
__global__ __launch_bounds__(256) void k_final(
    const float* __restrict__ wout, const float* __restrict__ hsrc,
    float* __restrict__ out) {
    __shared__ float As[16][64];
    __shared__ float Bs[16][64];
    int tid = threadIdx.x;
    int tx = tid & 15, ty = tid >> 4;
    int l0 = blockIdx.x * 64, o0 = blockIdx.y * 64;
    int arow = tid >> 2, ak = (tid & 3) * 4;
    float acc[4][4] = {};
    for (int k0 = 0; k0 < 128; k0 += 16) {
        float4 av = *(const float4*)(wout + (o0 + arow) * 128 + k0 + ak);
        As[ak + 0][arow] = av.x; As[ak + 1][arow] = av.y;
        As[ak + 2][arow] = av.z; As[ak + 3][arow] = av.w;
        float4 bv = *(const float4*)(g_yg + (l0 + arow) * 128 + k0 + ak);
        Bs[ak + 0][arow] = bv.x; Bs[ak + 1][arow] = bv.y;
        Bs[ak + 2][arow] = bv.z; Bs[ak + 3][arow] = bv.w;
        __syncthreads();
#pragma unroll
        for (int kk = 0; kk < 16; kk++) {
            float4 a = *(float4*)&As[kk][ty * 4];
            float4 b = *(float4*)&Bs[kk][tx * 4];
            float ar[4] = {a.x, a.y, a.z, a.w};
            float br[4] = {b.x, b.y, b.z, b.w};
#pragma unroll
            for (int r = 0; r < 4; r++)
#pragma unroll
                for (int cc = 0; cc < 4; cc++)
                    acc[r][cc] = fmaf(ar[r], br[cc], acc[r][cc]);
        }
        __syncthreads();
    }
#pragma unroll
    for (int r = 0; r < 4; r++) {
        int o = o0 + ty * 4 + r;
#pragma unroll
        for (int cc = 0; cc < 4; cc++) {
            int l = l0 + tx * 4 + cc;
            out[o * L + l] = hsrc[o * L + l] + tanhf(acc[r][cc]);
        }
    }
}

// ---------------- launch ----------------
extern "C" void kernel_launch(void* const* d_in, const int* in_sizes, int n_in,
                              void* d_out, int out_size) {
    const float* h       = (const float*)d_in[0];
    const float* x       = (const float*)d_in[1];
    const float* w_proj  = (const float*)d_in[2];
    const float* b_proj  = (const float*)d_in[3];
    const float* w_in    = (const float*)d_in[4];
    const float* w_conv  = (const float*)d_in[5];
    const float* b_conv  = (const float*)d_in[6];
    const float* x_proj_w= (const float*)d_in[7];
    const float* dt_w    = (const float*)d_in[8];
    const float* dt_b    = (const float*)d_in[9];
    const float* A_log   = (const float*)d_in[10];
    const float* D_ssm   = (const float*)d_in[11];
    const float* ln_g    = (const float*)d_in[12];
    const float* ln_b    = (const float*)d_in[13];
    const float* w_out   = (const float*)d_in[14];
    float* out = (float*)d_out;

    k_checkA<<<1, 1024>>>(A_log);
    k_gemm1 <<<dim3(128, 2), 256>>>(h, x, w_proj, b_proj);
    k_gemm2 <<<dim3(128, 4), 256>>>(w_in);
    k_convt <<<dim3(256, 4), dim3(32, 8)>>>(w_conv, b_conv);
    k_dbc   <<<dim3(128, 1, 4), 256>>>(x_proj_w);
    k_dt    <<<dim3(256, 4), 128>>>(dt_w, dt_b);
    k_scan1 <<<dim3(NCH, 4), 128>>>(A_log);
    k_scan2 <<<dim3(8, 4), 256>>>(A_log);
    k_scan3 <<<dim3(NCH, 4), 128>>>(A_log, D_ssm);
    k_merge <<<256, 256>>>(ln_g, ln_b);
    k_final <<<dim3(128, 2), 256>>>(w_out, h, out);
}

// round 9
// speedup vs baseline: 1.1274x; 1.0477x over previous
#include <cuda_runtime.h>
#include <math.h>

#define L    8192
#define DIN  128
#define HH   64
#define WW   128
#define NCH  64
#define LC   128

// ---------------- scratch (device globals; no allocation) ----------------
__device__ float g_hxp[DIN * L];        // after w_proj GEMM       [o][l]
__device__ float g_xp [DIN * L];        // xp pre-conv             [d][l]
__device__ float g_zt [L * DIN];        // z                       [l][d]
__device__ float g_xsr[L * DIN];        // row-major scan input    [l][d]
__device__ float g_xsc[L * DIN];        // col-major scan input    [lc][d]
__device__ float g_dtv[4 * L * DIN];    // softplus dt             [k][l][d]
__device__ float g_bc [4 * L * 32];     // B(16),C(16) per pos     [k][l][32]
__device__ float g_S  [4 * DIN * NCH];          // sum dt per chunk
__device__ float g_F  [4 * DIN * NCH * 16];     // chunk-local final state
__device__ float g_hi [4 * DIN * NCH * 16];     // chunk initial state
__device__ float g_ys [4 * L * DIN];    // scan outputs            [k][l][d]
__device__ float g_yg [L * DIN];        // merged+LN+gated         [l][d]
__device__ int   g_intA;

// ---------------- A-structure check: A_log == log(1..16)? ----------------
__global__ __launch_bounds__(1024) void k_checkA(const float* __restrict__ A_log) {
    __shared__ float ref[16];
    __shared__ int bad;
    int tid = threadIdx.x;
    if (tid < 16) ref[tid] = logf((float)(tid + 1));
    if (tid == 0) bad = 0;
    __syncthreads();
    for (int i = tid; i < 4 * DIN * 16; i += 1024)
        if (fabsf(A_log[i] - ref[i & 15]) > 1e-5f) bad = 1;
    __syncthreads();
    if (tid == 0) g_intA = bad ? 0 : 1;
}

// ---------------- GEMM1: hxp = w_proj @ concat(h,x) + b_proj -------------
__global__ __launch_bounds__(256) void k_gemm1(
    const float* __restrict__ hsrc, const float* __restrict__ xsrc,
    const float* __restrict__ w,    const float* __restrict__ bias) {
    __shared__ float As[16][64];
    __shared__ float Bs[16][64];
    int tid = threadIdx.x;
    int tx = tid & 15, ty = tid >> 4;
    int l0 = blockIdx.x * 64, o0 = blockIdx.y * 64;
    int arow = tid >> 2, ak = (tid & 3) * 4;
    int bk = tid >> 4, bj = (tid & 15) * 4;
    float acc[4][4] = {};
    for (int k0 = 0; k0 < 320; k0 += 16) {
        float4 av = *(const float4*)(w + (o0 + arow) * 320 + k0 + ak);
        As[ak + 0][arow] = av.x; As[ak + 1][arow] = av.y;
        As[ak + 2][arow] = av.z; As[ak + 3][arow] = av.w;
        int c = k0 + bk;
        const float* bp = (c < 128) ? (hsrc + c * L) : (xsrc + (c - 128) * L);
        *(float4*)&Bs[bk][bj] = *(const float4*)(bp + l0 + bj);
        __syncthreads();
#pragma unroll
        for (int kk = 0; kk < 16; kk++) {
            float4 a = *(float4*)&As[kk][ty * 4];
            float4 b = *(float4*)&Bs[kk][tx * 4];
            float ar[4] = {a.x, a.y, a.z, a.w};
            float br[4] = {b.x, b.y, b.z, b.w};
#pragma unroll
            for (int r = 0; r < 4; r++)
#pragma unroll
                for (int cc = 0; cc < 4; cc++)
                    acc[r][cc] = fmaf(ar[r], br[cc], acc[r][cc]);
        }
        __syncthreads();
    }
#pragma unroll
    for (int r = 0; r < 4; r++) {
        int o = o0 + ty * 4 + r;
        float bv = bias[o];
#pragma unroll
        for (int cc = 0; cc < 4; cc++)
            g_hxp[o * L + l0 + tx * 4 + cc] = acc[r][cc] + bv;
    }
}

// ---------------- GEMM2: xz = w_in @ hxp; split into xp / z^T ------------
__global__ __launch_bounds__(256) void k_gemm2(const float* __restrict__ w) {
    __shared__ float As[16][64];
    __shared__ float Bs[16][64];
    int tid = threadIdx.x;
    int tx = tid & 15, ty = tid >> 4;
    int l0 = blockIdx.x * 64, o0 = blockIdx.y * 64;
    int arow = tid >> 2, ak = (tid & 3) * 4;
    int bk = tid >> 4, bj = (tid & 15) * 4;
    float acc[4][4] = {};
    for (int k0 = 0; k0 < 128; k0 += 16) {
        float4 av = *(const float4*)(w + (o0 + arow) * 128 + k0 + ak);
        As[ak + 0][arow] = av.x; As[ak + 1][arow] = av.y;
        As[ak + 2][arow] = av.z; As[ak + 3][arow] = av.w;
        *(float4*)&Bs[bk][bj] = *(const float4*)(g_hxp + (k0 + bk) * L + l0 + bj);
        __syncthreads();
#pragma unroll
        for (int kk = 0; kk < 16; kk++) {
            float4 a = *(float4*)&As[kk][ty * 4];
            float4 b = *(float4*)&Bs[kk][tx * 4];
            float ar[4] = {a.x, a.y, a.z, a.w};
            float br[4] = {b.x, b.y, b.z, b.w};
#pragma unroll
            for (int r = 0; r < 4; r++)
#pragma unroll
                for (int cc = 0; cc < 4; cc++)
                    acc[r][cc] = fmaf(ar[r], br[cc], acc[r][cc]);
        }
        __syncthreads();
    }
#pragma unroll
    for (int r = 0; r < 4; r++) {
        int o = o0 + ty * 4 + r;
#pragma unroll
        for (int cc = 0; cc < 4; cc++) {
            int l = l0 + tx * 4 + cc;
            float v = acc[r][cc];
            if (o < 128) g_xp[o * L + l] = v;
            else         g_zt[l * DIN + (o - 128)] = v;
        }
    }
}

// ------------- fused depthwise 3x3 conv + SiLU + transpose (branchless) --
__global__ void k_convt(const float* __restrict__ wc,
                        const float* __restrict__ bcv) {
    __shared__ float t[32][33];
    int l0 = blockIdx.x * 32, d0 = blockIdx.y * 32;
    int tx = threadIdx.x, ty = threadIdx.y;  // 32 x 8
    int l = l0 + tx;
    int hh = l >> 7, ww = l & 127;
    bool top = hh > 0, bot = hh < HH - 1, lft = ww > 0, rgt = ww < WW - 1;
#pragma unroll
    for (int j = 0; j < 4; j++) {
        int d = d0 + ty + 8 * j;
        const float* s = g_xp + (d << 13) + l;
        const float* w9 = wc + d * 9;
        float acc = bcv[d];
        acc = fmaf(top && lft ? s[-129] : 0.f, w9[0], acc);
        acc = fmaf(top        ? s[-128] : 0.f, w9[1], acc);
        acc = fmaf(top && rgt ? s[-127] : 0.f, w9[2], acc);
        acc = fmaf(lft        ? s[-1]   : 0.f, w9[3], acc);
        acc = fmaf(             s[0],          w9[4], acc);
        acc = fmaf(rgt        ? s[1]    : 0.f, w9[5], acc);
        acc = fmaf(bot && lft ? s[127]  : 0.f, w9[6], acc);
        acc = fmaf(bot        ? s[128]  : 0.f, w9[7], acc);
        acc = fmaf(bot && rgt ? s[129]  : 0.f, w9[8], acc);
        t[ty + 8 * j][tx] = acc / (1.f + __expf(-acc));
    }
    __syncthreads();
#pragma unroll
    for (int j = 0; j < 4; j++) {
        int l2 = l0 + ty + 8 * j;
        float v = t[tx][ty + 8 * j];
        g_xsr[l2 * DIN + d0 + tx] = v;
        int h2 = l2 >> 7, w2 = l2 & 127;
        g_xsc[(w2 * HH + h2) * DIN + d0 + tx] = v;
    }
}

// ---- fused x_proj (paired k/k+2, M=80) + dt(softplus) + B/C pack --------
// pair p: k = p uses source forward; kr = p+2 is the same GEMM with output
// index reversed (dbc[kr][r][l] = E[40+r][L-1-l]).
__global__ __launch_bounds__(256) void k_dbcdt(
    const float* __restrict__ xpw, const float* __restrict__ dtw,
    const float* __restrict__ dtbias) {
    __shared__ float As[16][80];
    __shared__ float Bs[16][64];
    __shared__ float Eo[80][66];
    int p = blockIdx.y;
    int k = p, kr = p + 2;
    const float* Bsrc = p ? g_xsc : g_xsr;
    const float* A0 = xpw + k  * 40 * 128;
    const float* A1 = xpw + kr * 40 * 128;
    int tid = threadIdx.x;
    int tx = tid & 15, ty = tid >> 4;       // ty: 5 rows each; tx: 4 l
    int l0 = blockIdx.x * 64;
    int bl = tid >> 2, bc4 = (tid & 3) * 4;
    float acc[5][4] = {};
    for (int k0 = 0; k0 < 128; k0 += 16) {
        for (int i = tid; i < 320; i += 256) {
            int row = i >> 2, kc = (i & 3) * 4;
            const float* ap = (row < 40) ? (A0 + row * 128)
                                         : (A1 + (row - 40) * 128);
            float4 av = *(const float4*)(ap + k0 + kc);
            As[kc + 0][row] = av.x; As[kc + 1][row] = av.y;
            As[kc + 2][row] = av.z; As[kc + 3][row] = av.w;
        }
        {
            float4 bv = *(const float4*)(Bsrc + (l0 + bl) * 128 + k0 + bc4);
            Bs[bc4 + 0][bl] = bv.x; Bs[bc4 + 1][bl] = bv.y;
            Bs[bc4 + 2][bl] = bv.z; Bs[bc4 + 3][bl] = bv.w;
        }
        __syncthreads();
#pragma unroll
        for (int kk = 0; kk < 16; kk++) {
            float a5[5];
#pragma unroll
            for (int r = 0; r < 5; r++) a5[r] = As[kk][ty * 5 + r];
            float4 b = *(float4*)&Bs[kk][tx * 4];
            float br[4] = {b.x, b.y, b.z, b.w};
#pragma unroll
            for (int r = 0; r < 5; r++)
#pragma unroll
                for (int cc = 0; cc < 4; cc++)
                    acc[r][cc] = fmaf(a5[r], br[cc], acc[r][cc]);
        }
        __syncthreads();
    }
#pragma unroll
    for (int r = 0; r < 5; r++)
#pragma unroll
        for (int cc = 0; cc < 4; cc++)
            Eo[ty * 5 + r][tx * 4 + cc] = acc[r][cc];
    __syncthreads();

    // dt = softplus(dtw @ rows{0..7 | 40..47} + bias), both directions
    {
        int d = tid & 127, half = tid >> 7;
        float w0[8], w1[8];
#pragma unroll
        for (int r = 0; r < 8; r++) {
            w0[r] = dtw[(k  * DIN + d) * 8 + r];
            w1[r] = dtw[(kr * DIN + d) * 8 + r];
        }
        float b0v = dtbias[k * DIN + d], b1v = dtbias[kr * DIN + d];
        for (int jj = 0; jj < 32; jj++) {
            int j = half * 32 + jj;
            float a0 = b0v, a1 = b1v;
#pragma unroll
            for (int r = 0; r < 8; r++) {
                a0 = fmaf(w0[r], Eo[r][j], a0);
                a1 = fmaf(w1[r], Eo[40 + r][j], a1);
            }
            float sp0 = (a0 > 20.f) ? a0 : log1pf(__expf(a0));
            float sp1 = (a1 > 20.f) ? a1 : log1pf(__expf(a1));
            g_dtv[(k * L + l0 + j) * DIN + d] = sp0;
            g_dtv[(kr * L + (L - 1 - l0 - j)) * DIN + d] = sp1;
        }
    }
    // pack B(16),C(16) for both directions
    for (int i = tid; i < 2048; i += 256) {
        int n = i & 31, j = i >> 5;
        g_bc[(k * L + l0 + j) * 32 + n] = Eo[8 + n][j];
        g_bc[(kr * L + (L - 1 - l0 - j)) * 32 + n] = Eo[48 + n][j];
    }
}

// ---------------- a_n = exp(dt * A_n) helpers ----------------------------
__device__ __forceinline__ void compute_a(float dtv, const float* An, bool ia,
                                          float* a) {
    if (ia) {  // A_n = -(n+1): a_n = r^(n+1), r = exp(-dt)
        float r1 = __expf(-dtv);
        float r2 = r1 * r1, r4 = r2 * r2, r8 = r4 * r4;
        a[0] = r1;       a[1] = r2;       a[2] = r2 * r1;  a[3] = r4;
        a[4] = r4 * r1;  a[5] = r4 * r2;  a[6] = r4 * a[2]; a[7] = r8;
        a[8] = r8 * r1;  a[9] = r8 * r2;  a[10] = r8 * a[2]; a[11] = r8 * r4;
        a[12] = r8 * a[4]; a[13] = r8 * a[5]; a[14] = r8 * a[6]; a[15] = r8 * r8;
    } else {
#pragma unroll
        for (int n = 0; n < 16; n++) a[n] = __expf(An[n] * dtv);
    }
}

// ---------------- scan phase 1: chunk-local (F, sum-dt) ------------------
__global__ __launch_bounds__(128) void k_scan1(const float* __restrict__ A_log) {
    int c = blockIdx.x, k = blockIdx.y, d = threadIdx.x;
    bool ia = (g_intA != 0);
    float An[16];
    if (!ia) {
#pragma unroll
        for (int n = 0; n < 16; n++) An[n] = -__expf(A_log[(k * DIN + d) * 16 + n]);
    }
    const float* usrc = (k & 1) ? g_xsc : g_xsr;
    bool rev = (k >= 2);
    float hr[16];
#pragma unroll
    for (int n = 0; n < 16; n++) hr[n] = 0.f;
    float S = 0.f;
    const float* dtp = g_dtv + k * L * DIN;
    for (int i = 0; i < LC; i++) {
        int l = c * LC + i;
        float dtv = dtp[l * DIN + d];
        int lu = rev ? (L - 1 - l) : l;
        float uv = usrc[lu * DIN + d];
        float du = dtv * uv;
        S += dtv;
        const float4* bp = (const float4*)(g_bc + (k * L + l) * 32);
        float4 b0 = bp[0], b1 = bp[1], b2 = bp[2], b3 = bp[3];
        float bb[16] = {b0.x, b0.y, b0.z, b0.w, b1.x, b1.y, b1.z, b1.w,
                        b2.x, b2.y, b2.z, b2.w, b3.x, b3.y, b3.z, b3.w};
        float a[16];
        compute_a(dtv, An, ia, a);
#pragma unroll
        for (int n = 0; n < 16; n++) hr[n] = fmaf(a[n], hr[n], du * bb[n]);
    }
    int base = (k * DIN + d) * NCH + c;
    g_S[base] = S;
#pragma unroll
    for (int n = 0; n < 16; n++) g_F[base * 16 + n] = hr[n];
}

// ---------------- scan phase 2: cross-chunk prefix -----------------------
__global__ __launch_bounds__(256) void k_scan2(const float* __restrict__ A_log) {
    int n = threadIdx.x & 15;
    int d = blockIdx.x * 16 + (threadIdx.x >> 4);
    int k = blockIdx.y;
    bool ia = (g_intA != 0);
    float An = ia ? -(float)(n + 1) : -__expf(A_log[(k * DIN + d) * 16 + n]);
    float h = 0.f;
    int base = (k * DIN + d) * NCH;
    for (int c = 0; c < NCH; c++) {
        g_hi[(base + c) * 16 + n] = h;
        float P = __expf(An * g_S[base + c]);
        h = fmaf(P, h, g_F[(base + c) * 16 + n]);
    }
}

// ---------------- scan phase 3: replay with init, emit y -----------------
__global__ __launch_bounds__(128) void k_scan3(
    const float* __restrict__ A_log, const float* __restrict__ Dssm) {
    int c = blockIdx.x, k = blockIdx.y, d = threadIdx.x;
    bool ia = (g_intA != 0);
    float An[16];
    if (!ia) {
#pragma unroll
        for (int n = 0; n < 16; n++) An[n] = -__expf(A_log[(k * DIN + d) * 16 + n]);
    }
    const float* usrc = (k & 1) ? g_xsc : g_xsr;
    bool rev = (k >= 2);
    float Dv = Dssm[k * DIN + d];
    int base = (k * DIN + d) * NCH + c;
    float hr[16];
#pragma unroll
    for (int n = 0; n < 16; n++) hr[n] = g_hi[base * 16 + n];
    const float* dtp = g_dtv + k * L * DIN;
    for (int i = 0; i < LC; i++) {
        int l = c * LC + i;
        float dtv = dtp[l * DIN + d];
        int lu = rev ? (L - 1 - l) : l;
        float uv = usrc[lu * DIN + d];
        float du = dtv * uv;
        const float4* bp = (const float4*)(g_bc + (k * L + l) * 32);
        float4 b0 = bp[0], b1 = bp[1], b2 = bp[2], b3 = bp[3];
        float4 c0 = bp[4], c1 = bp[5], c2 = bp[6], c3 = bp[7];
        float bb[16] = {b0.x, b0.y, b0.z, b0.w, b1.x, b1.y, b1.z, b1.w,
                        b2.x, b2.y, b2.z, b2.w, b3.x, b3.y, b3.z, b3.w};
        float cc[16] = {c0.x, c0.y, c0.z, c0.w, c1.x, c1.y, c1.z, c1.w,
                        c2.x, c2.y, c2.z, c2.w, c3.x, c3.y, c3.z, c3.w};
        float a[16];
        compute_a(dtv, An, ia, a);
        float y4[4] = {0.f, 0.f, 0.f, 0.f};
#pragma unroll
        for (int n = 0; n < 16; n++) {
            hr[n] = fmaf(a[n], hr[n], du * bb[n]);
            y4[n & 3] = fmaf(hr[n], cc[n], y4[n & 3]);
        }
        float y = fmaf(Dv, uv, (y4[0] + y4[1]) + (y4[2] + y4[3]));
        g_ys[(k * L + l) * DIN + d] = y;
    }
}

// ---------------- cross-merge + LN + SiLU(z) gate -> yg[l][d] ------------
__global__ __launch_bounds__(256) void k_merge(
    const float* __restrict__ lng, const float* __restrict__ lnb) {
    int l0 = blockIdx.x * 32;
    int lane = threadIdx.x & 31, w = threadIdx.x >> 5;
    float g4[4], b4[4];
    *(float4*)g4 = *(const float4*)(lng + lane * 4);
    *(float4*)b4 = *(const float4*)(lnb + lane * 4);
#pragma unroll
    for (int q = 0; q < 4; q++) {
        int l = l0 + w * 4 + q;
        int hh = l >> 7, ww = l & 127;
        int lc = ww * HH + hh;
        float4 y0 = *(const float4*)(g_ys + (0 * L + l) * DIN + lane * 4);
        float4 y2 = *(const float4*)(g_ys + (2 * L + (L - 1 - l)) * DIN + lane * 4);
        float4 y1 = *(const float4*)(g_ys + (1 * L + lc) * DIN + lane * 4);
        float4 y3 = *(const float4*)(g_ys + (3 * L + (L - 1 - lc)) * DIN + lane * 4);
        float yv[4] = {y0.x + y2.x + y1.x + y3.x, y0.y + y2.y + y1.y + y3.y,
                       y0.z + y2.z + y1.z + y3.z, y0.w + y2.w + y1.w + y3.w};
        float s = yv[0] + yv[1] + yv[2] + yv[3];
        float s2 = yv[0] * yv[0] + yv[1] * yv[1] + yv[2] * yv[2] + yv[3] * yv[3];
#pragma unroll
        for (int o = 16; o > 0; o >>= 1) {
            s  += __shfl_xor_sync(0xffffffffu, s, o);
            s2 += __shfl_xor_sync(0xffffffffu, s2, o);
        }
        float mu = s * (1.f / 128.f);
        float var = s2 * (1.f / 128.f) - mu * mu;
        float rstd = rsqrtf(var + 1e-5f);
        float4 zv = *(const float4*)(g_zt + l * DIN + lane * 4);
        float zz[4] = {zv.x, zv.y, zv.z, zv.w};
        float4 ov;
        float* op = (float*)&ov;
#pragma unroll
        for (int m = 0; m < 4; m++) {
            float gv = (yv[m] - mu) * rstd * g4[m] + b4[m];
            float sz = zz[m] / (1.f + __expf(-zz[m]));
            op[m] = gv * sz;
        }
        *(float4*)(g_yg + l * DIN + lane * 4) = ov;
    }
}

// ---------------- final: out = h + tanh(w_out @ yg)  (NT GEMM) -----------
__global__ __launch_bounds__(256) void k_final(
    const float* __restrict__ wout, const float* __restrict__ hsrc,
    float* __restrict__ out) {
    __shared__ float As[16][64];
    __shared__ float Bs[16][64];
    int tid = threadIdx.x;
    int tx = tid & 15, ty = tid >> 4;
    int l0 = blockIdx.x * 64, o0 = blockIdx.y * 64;
    int arow = tid >> 2, ak = (tid & 3) * 4;
    float acc[4][4] = {};
    for (int k0 = 0; k0 < 128; k0 += 16) {
        float4 av = *(const float4*)(wout + (o0 + arow) * 128 + k0 + ak);
        As[ak + 0][arow] = av.x; As[ak + 1][arow] = av.y;
        As[ak + 2][arow] = av.z; As[ak + 3][arow] = av.w;
        float4 bv = *(const float4*)(g_yg + (l0 + arow) * 128 + k0 + ak);
        Bs[ak + 0][arow] = bv.x; Bs[ak + 1][arow] = bv.y;
        Bs[ak + 2][arow] = bv.z; Bs[ak + 3][arow] = bv.w;
        __syncthreads();
#pragma unroll
        for (int kk = 0; kk < 16; kk++) {
            float4 a = *(float4*)&As[kk][ty * 4];
            float4 b = *(float4*)&Bs[kk][tx * 4];
            float ar[4] = {a.x, a.y, a.z, a.w};
            float br[4] = {b.x, b.y, b.z, b.w};
#pragma unroll
            for (int r = 0; r < 4; r++)
#pragma unroll
                for (int cc = 0; cc < 4; cc++)
                    acc[r][cc] = fmaf(ar[r], br[cc], acc[r][cc]);
        }
        __syncthreads();
    }
#pragma unroll
    for (int r = 0; r < 4; r++) {
        int o = o0 + ty * 4 + r;
#pragma unroll
        for (int cc = 0; cc < 4; cc++) {
            int l = l0 + tx * 4 + cc;
            out[o * L + l] = hsrc[o * L + l] + tanhf(acc[r][cc]);
        }
    }
}

// ---------------- launch ----------------
extern "C" void kernel_launch(void* const* d_in, const int* in_sizes, int n_in,
                              void* d_out, int out_size) {
    const float* h       = (const float*)d_in[0];
    const float* x       = (const float*)d_in[1];
    const float* w_proj  = (const float*)d_in[2];
    const float* b_proj  = (const float*)d_in[3];
    const float* w_in    = (const float*)d_in[4];
    const float* w_conv  = (const float*)d_in[5];
    const float* b_conv  = (const float*)d_in[6];
    const float* x_proj_w= (const float*)d_in[7];
    const float* dt_w    = (const float*)d_in[8];
    const float* dt_b    = (const float*)d_in[9];
    const float* A_log   = (const float*)d_in[10];
    const float* D_ssm   = (const float*)d_in[11];
    const float* ln_g    = (const float*)d_in[12];
    const float* ln_b    = (const float*)d_in[13];
    const float* w_out   = (const float*)d_in[14];
    float* out = (float*)d_out;

    k_checkA<<<1, 1024>>>(A_log);
    k_gemm1 <<<dim3(128, 2), 256>>>(h, x, w_proj, b_proj);
    k_gemm2 <<<dim3(128, 4), 256>>>(w_in);
    k_convt <<<dim3(256, 4), dim3(32, 8)>>>(w_conv, b_conv);
    k_dbcdt <<<dim3(128, 2), 256>>>(x_proj_w, dt_w, dt_b);
    k_scan1 <<<dim3(NCH, 4), 128>>>(A_log);
    k_scan2 <<<dim3(8, 4), 256>>>(A_log);
    k_scan3 <<<dim3(NCH, 4), 128>>>(A_log, D_ssm);
    k_merge <<<256, 256>>>(ln_g, ln_b);
    k_final <<<dim3(128, 2), 256>>>(w_out, h, out);
}